// round 9
// baseline (speedup 1.0000x reference)
#include <cuda_runtime.h>
#include <cstdint>

// ---------------------------------------------------------------------------
// _LSTMOneMany_3289944948986 : 2-layer GRU decoder, B=512, H=2048, O=512, T=32.
// tf32 mma.sync GEMMs (tcgen05 unavailable: harness targets sm_103 family).
// Round 9: 64x128 CTA tiles (256 thr, 8 warps, 32x32 warp tiles) -> grid
// doubles, 2 CTAs/SM resident, 4 warps/SMSP. 3-stage cp.async (27.6KB/stage),
// PAD=36 + ldmatrix (validated in R8). R5 loop structure.
// ---------------------------------------------------------------------------

#define BSZ   512
#define HID   2048
#define OUTD  512
#define G3H   6144
#define GLD   12288
#define KSPLIT 8
#define PAD   36                     // padded floats per 32-col tile row
#define TM    64                     // CTA tile M
#define TN    128                    // CTA tile N

// ---- scratch (__device__ globals; no allocation allowed) ----
__device__ __align__(16) float g_g   [BSZ * GLD];     // gate pre-activations
__device__ __align__(16) float g_h0  [BSZ * HID];     // exact fp32 state
__device__ __align__(16) float g_h1  [BSZ * HID];
__device__ __align__(16) float g_h0r [BSZ * HID];     // tf32-rounded GEMM copies
__device__ __align__(16) float g_h1r [BSZ * HID];
__device__ __align__(16) float g_outr[BSZ * OUTD];    // rounded feedback input
__device__ __align__(16) float g_part[KSPLIT * BSZ * OUTD];

// tf32-rounded weights / inputs
__device__ __align__(16) float w_x   [BSZ * 2 * 1024];
__device__ __align__(16) float w_emb [2048 * 1024];
__device__ __align__(16) float w_ih0 [G3H * OUTD];
__device__ __align__(16) float w_hh0 [G3H * HID];
__device__ __align__(16) float w_ih1 [G3H * HID];
__device__ __align__(16) float w_hh1 [G3H * HID];
__device__ __align__(16) float w_out [OUTD * HID];

// ---------------------------------------------------------------------------
__device__ __forceinline__ float roundtf(float x) {
    uint32_t u;
    asm("cvt.rna.tf32.f32 %0, %1;" : "=r"(u) : "f"(x));
    return __uint_as_float(u);
}

// ---------------------------------------------------------------------------
// GEMM: C[M,N] = A[M,K] @ B[N,K]^T, operands already tf32-rounded fp32.
// 64x128 CTA tile, 256 threads (8 warps, 2x4 grid of 32x32 warp tiles),
// 3-stage cp.async pipeline, 2 CTAs/SM. PAD=36 layout + ldmatrix b16 frags.
// MODE 0: raw store.  MODE 2: embedding (bias+relu, scatter h0/h1 + rounded).
// MODE 3: split-K partial (blockIdx.z slice of K) into g_part.
// ---------------------------------------------------------------------------
#define STAGE_FLTS ((TM + TN) * PAD)               // 6912 floats
#define STAGE_BYTES (STAGE_FLTS * 4)               // 27648
static const int SMEM_BYTES = 3 * STAGE_BYTES;     // 82944

template <int MODE>
__global__ void __launch_bounds__(256, 2)
gemm_tf32(const float* __restrict__ A0, int lda0,
          const float* __restrict__ B0, int ldb0, int K0,
          const float* __restrict__ A1, int lda1,
          const float* __restrict__ B1, int ldb1, int K1,
          int nSplit,
          float* __restrict__ C, int ldc,
          const float* __restrict__ bias)
{
    extern __shared__ float smem[];   // [3][A 64x36 | B 128x36]

    const int tid = threadIdx.x;
    const int bn  = blockIdx.x;
    const int bm  = blockIdx.y;
    const int nBase = bn * TN;

    const float* A; const float* B; int lda, ldb, K;
    if (nBase < nSplit) {
        A = A0; lda = lda0; B = B0 + (size_t)nBase * ldb0; ldb = ldb0; K = K0;
    } else {
        A = A1; lda = lda1; B = B1 + (size_t)(nBase - nSplit) * ldb1; ldb = ldb1; K = K1;
    }
    A += (size_t)bm * TM * lda;
    if (MODE == 3) {
        int koff = blockIdx.z * K;
        A += koff; B += koff;
        C += (size_t)blockIdx.z * (BSZ * OUTD);
    }

    const int lane = tid & 31;
    const int warp = tid >> 5;
    const int wm = (warp >> 2) << 5;   // 0 / 32
    const int wn = (warp & 3) << 5;    // 0,32,64,96
    const int lr = lane >> 2;          // 0..7
    const int lc = lane & 3;           // 0..3

    // ldmatrix per-lane addresses (bytes, shared space)
    const uint32_t smemBase = (uint32_t)__cvta_generic_to_shared(smem);
    const int lrow = lane & 7, lblk = (lane >> 3) & 1, lcol = (lane >> 4) & 1;
    const uint32_t aLdm = smemBase +
        (uint32_t)(((wm + lrow + lblk * 8) * PAD + lcol * 4) * 4);
    const uint32_t bLdm = smemBase +
        (uint32_t)((TM * PAD + (wn + lrow + lblk * 8) * PAD + lcol * 4) * 4);

    float acc[2][4][4];
#pragma unroll
    for (int i = 0; i < 2; i++)
#pragma unroll
        for (int j = 0; j < 4; j++)
#pragma unroll
            for (int k = 0; k < 4; k++) acc[i][j][k] = 0.f;

    auto load_stage = [&](int buf, int k0) {
        float* sA = smem + buf * STAGE_FLTS;
        float* sB = sA + TM * PAD;
        // A: 64 rows x 8 chunks = 512 slots, 2 per thread
#pragma unroll
        for (int it = 0; it < 2; it++) {
            int idx = tid + it * 256;
            int row = idx >> 3, cc = idx & 7;
            uint32_t d = (uint32_t)__cvta_generic_to_shared(&sA[row * PAD + cc * 4]);
            asm volatile("cp.async.cg.shared.global [%0], [%1], 16;\n"
                         :: "r"(d), "l"(A + (size_t)row * lda + k0 + cc * 4));
        }
        // B: 128 rows x 8 chunks = 1024 slots, 4 per thread
#pragma unroll
        for (int it = 0; it < 4; it++) {
            int idx = tid + it * 256;
            int row = idx >> 3, cc = idx & 7;
            uint32_t d = (uint32_t)__cvta_generic_to_shared(&sB[row * PAD + cc * 4]);
            asm volatile("cp.async.cg.shared.global [%0], [%1], 16;\n"
                         :: "r"(d), "l"(B + (size_t)row * ldb + k0 + cc * 4));
        }
        asm volatile("cp.async.commit_group;\n");
    };

    const int nStages = K >> 5;        // K multiple of 64 everywhere -> >= 2
    load_stage(0, 0);
    if (nStages > 1) load_stage(1, 32);
    int buf = 0;

    for (int st = 0; st < nStages; st++) {
        if (st + 2 < nStages) {
            load_stage((st + 2) % 3, (st + 2) * 32);
            asm volatile("cp.async.wait_group 2;\n");
        } else if (st + 1 < nStages) {
            asm volatile("cp.async.wait_group 1;\n");
        } else {
            asm volatile("cp.async.wait_group 0;\n");
        }
        __syncthreads();

        const uint32_t stOff = (uint32_t)(buf * STAGE_BYTES);
        const uint32_t aS = aLdm + stOff;
        const uint32_t bS = bLdm + stOff;

#pragma unroll
        for (int kk = 0; kk < 4; kk++) {
            const uint32_t kOff = kk * 32;           // 8 floats
            uint32_t af[2][4], bf[4][2];
#pragma unroll
            for (int mt = 0; mt < 2; mt++) {
                asm volatile(
                    "ldmatrix.sync.aligned.m8n8.x4.shared.b16 {%0,%1,%2,%3}, [%4];\n"
                    : "=r"(af[mt][0]), "=r"(af[mt][1]),
                      "=r"(af[mt][2]), "=r"(af[mt][3])
                    : "r"(aS + (uint32_t)(mt * 16 * PAD * 4) + kOff));
            }
#pragma unroll
            for (int n2 = 0; n2 < 2; n2++) {
                asm volatile(
                    "ldmatrix.sync.aligned.m8n8.x4.shared.b16 {%0,%1,%2,%3}, [%4];\n"
                    : "=r"(bf[2 * n2][0]), "=r"(bf[2 * n2 + 1][0]),
                      "=r"(bf[2 * n2][1]), "=r"(bf[2 * n2 + 1][1])
                    : "r"(bS + (uint32_t)(n2 * 16 * PAD * 4) + kOff));
            }
#pragma unroll
            for (int mt = 0; mt < 2; mt++)
#pragma unroll
                for (int nt = 0; nt < 4; nt++) {
                    float* c = acc[mt][nt];
                    asm volatile(
                        "mma.sync.aligned.m16n8k8.row.col.f32.tf32.tf32.f32 "
                        "{%0,%1,%2,%3}, {%4,%5,%6,%7}, {%8,%9}, {%0,%1,%2,%3};\n"
                        : "+f"(c[0]), "+f"(c[1]), "+f"(c[2]), "+f"(c[3])
                        : "r"(af[mt][0]), "r"(af[mt][1]), "r"(af[mt][2]), "r"(af[mt][3]),
                          "r"(bf[nt][0]), "r"(bf[nt][1]));
                }
        }
        __syncthreads();
        buf = (buf + 1) % 3;
    }

    // -------- epilogue --------
#pragma unroll
    for (int mt = 0; mt < 2; mt++)
#pragma unroll
        for (int nt = 0; nt < 4; nt++) {
            int m = bm * TM + wm + mt * 16 + lr;
            int n = nBase + wn + nt * 8 + lc * 2;
            float2 v0 = make_float2(acc[mt][nt][0], acc[mt][nt][1]);
            float2 v1 = make_float2(acc[mt][nt][2], acc[mt][nt][3]);
            if (MODE == 0 || MODE == 3) {
                *(float2*)&C[(size_t)m       * ldc + n] = v0;
                *(float2*)&C[(size_t)(m + 8) * ldc + n] = v1;
            } else {  // MODE 2: embedding -> relu; scatter to h0/h1 (+ rounded)
                float b0 = bias[n], b1 = bias[n + 1];
                v0.x = fmaxf(v0.x + b0, 0.f); v0.y = fmaxf(v0.y + b1, 0.f);
                v1.x = fmaxf(v1.x + b0, 0.f); v1.y = fmaxf(v1.y + b1, 0.f);
                float* hp = (m & 1) ? g_h1  : g_h0;
                float* hr = (m & 1) ? g_h1r : g_h0r;
                size_t o0 = (size_t)(m >> 1) * HID + n;
                size_t o1 = o0 + 4 * HID;              // rows m, m+8 same parity
                *(float2*)&hp[o0] = v0;
                *(float2*)&hp[o1] = v1;
                *(float2*)&hr[o0] = make_float2(roundtf(v0.x), roundtf(v0.y));
                *(float2*)&hr[o1] = make_float2(roundtf(v1.x), roundtf(v1.y));
            }
        }
}

// ---------------------------------------------------------------------------
// GRU gates (float4): r=sig(gx_r+gh_r), z=sig(gx_z+gh_z), n=tanh(gx_n+r*gh_n),
//                     h = (1-z)*n + z*h.  Writes exact fp32 h + rounded copy.
// ---------------------------------------------------------------------------
__global__ void __launch_bounds__(256)
gru_gates(const float* __restrict__ g,
          const float* __restrict__ bih, const float* __restrict__ bhh,
          float* __restrict__ h, float* __restrict__ hr, int hasGx)
{
    int idx = (blockIdx.x * 256 + threadIdx.x) * 4;   // < 512*2048
    int b = idx >> 11, j = idx & 2047;
    const float* gb = g + (size_t)b * GLD;

    float4 gxr = *(const float4*)&bih[j];
    float4 gxz = *(const float4*)&bih[HID + j];
    float4 gxn = *(const float4*)&bih[2 * HID + j];
    if (hasGx) {
        float4 a = *(const float4*)&gb[j];
        float4 c = *(const float4*)&gb[HID + j];
        float4 d = *(const float4*)&gb[2 * HID + j];
        gxr.x += a.x; gxr.y += a.y; gxr.z += a.z; gxr.w += a.w;
        gxz.x += c.x; gxz.y += c.y; gxz.z += c.z; gxz.w += c.w;
        gxn.x += d.x; gxn.y += d.y; gxn.z += d.z; gxn.w += d.w;
    }
    float4 ghr = *(const float4*)&gb[G3H + j];
    float4 ghz = *(const float4*)&gb[G3H + HID + j];
    float4 ghn = *(const float4*)&gb[G3H + 2 * HID + j];
    float4 br  = *(const float4*)&bhh[j];
    float4 bz  = *(const float4*)&bhh[HID + j];
    float4 bn  = *(const float4*)&bhh[2 * HID + j];
    float4 hp  = *(const float4*)&h[idx];

    float4 ho, hro;
#pragma unroll
    for (int q = 0; q < 4; q++) {
        float xr = ((float*)&gxr)[q], xz = ((float*)&gxz)[q], xn = ((float*)&gxn)[q];
        float vr = ((float*)&ghr)[q] + ((float*)&br)[q];
        float vz = ((float*)&ghz)[q] + ((float*)&bz)[q];
        float vn = ((float*)&ghn)[q] + ((float*)&bn)[q];
        float r = 1.f / (1.f + expf(-(xr + vr)));
        float z = 1.f / (1.f + expf(-(xz + vz)));
        float n = tanhf(xn + r * vn);
        float hv = (1.f - z) * n + z * ((float*)&hp)[q];
        ((float*)&ho)[q]  = hv;
        ((float*)&hro)[q] = roundtf(hv);
    }
    *(float4*)&h[idx]  = ho;
    *(float4*)&hr[idx] = hro;
}

// Reduce split-K partials + bias -> exact preds slice + rounded feedback buf.
__global__ void __launch_bounds__(256)
out_reduce(const float* __restrict__ outB, float* __restrict__ preds)
{
    int idx = (blockIdx.x * 256 + threadIdx.x) * 4;   // < 512*512
    int o = idx & 511, b = idx >> 9;
    float4 v = *(const float4*)&outB[o];
#pragma unroll
    for (int z = 0; z < KSPLIT; z++) {
        float4 pz = *(const float4*)&g_part[z * (BSZ * OUTD) + idx];
        v.x += pz.x; v.y += pz.y; v.z += pz.z; v.w += pz.w;
    }
    *(float4*)&preds[(size_t)b * (32 * OUTD) + o] = v;
    *(float4*)&g_outr[idx] =
        make_float4(roundtf(v.x), roundtf(v.y), roundtf(v.z), roundtf(v.w));
}

// fp32 -> tf32-rounded fp32, 4 segments per launch
__global__ void __launch_bounds__(256)
conv4(const float* s0, float* d0, int n0, const float* s1, float* d1, int n1,
      const float* s2, float* d2, int n2, const float* s3, float* d3, int n3)
{
    int i = blockIdx.x * 256 + threadIdx.x;
    if      (i < n0)         d0[i] = roundtf(s0[i]);
    else if ((i -= n0) < n1) d1[i] = roundtf(s1[i]);
    else if ((i -= n1) < n2) d2[i] = roundtf(s2[i]);
    else if ((i -= n2) < n3) d3[i] = roundtf(s3[i]);
}

// ---------------------------------------------------------------------------

extern "C" void kernel_launch(void* const* d_in, const int* in_sizes, int n_in,
                              void* d_out, int out_size)
{
    const float* x    = (const float*)d_in[0];
    const float* embB = (const float*)d_in[2];
    const float* bih0 = (const float*)d_in[5];
    const float* bhh0 = (const float*)d_in[6];
    const float* bih1 = (const float*)d_in[9];
    const float* bhh1 = (const float*)d_in[10];
    const float* outB = (const float*)d_in[12];
    float* out = (float*)d_out;                  // [512, 32, 512]

    cudaFuncSetAttribute(gemm_tf32<0>,
                         cudaFuncAttributeMaxDynamicSharedMemorySize, SMEM_BYTES);
    cudaFuncSetAttribute(gemm_tf32<2>,
                         cudaFuncAttributeMaxDynamicSharedMemorySize, SMEM_BYTES);
    cudaFuncSetAttribute(gemm_tf32<3>,
                         cudaFuncAttributeMaxDynamicSharedMemorySize, SMEM_BYTES);

    void* p;
    cudaGetSymbolAddress(&p, g_g);    float* g    = (float*)p;
    cudaGetSymbolAddress(&p, g_h0);   float* h0   = (float*)p;
    cudaGetSymbolAddress(&p, g_h1);   float* h1   = (float*)p;
    cudaGetSymbolAddress(&p, g_h0r);  float* h0r  = (float*)p;
    cudaGetSymbolAddress(&p, g_h1r);  float* h1r  = (float*)p;
    cudaGetSymbolAddress(&p, g_outr); float* outr = (float*)p;
    cudaGetSymbolAddress(&p, g_part); float* part = (float*)p;
    cudaGetSymbolAddress(&p, w_x);    float* xr   = (float*)p;
    cudaGetSymbolAddress(&p, w_emb);  float* eW   = (float*)p;
    cudaGetSymbolAddress(&p, w_ih0);  float* i0   = (float*)p;
    cudaGetSymbolAddress(&p, w_hh0);  float* r0   = (float*)p;
    cudaGetSymbolAddress(&p, w_ih1);  float* i1   = (float*)p;
    cudaGetSymbolAddress(&p, w_hh1);  float* r1   = (float*)p;
    cudaGetSymbolAddress(&p, w_out);  float* oW   = (float*)p;

    const int BIG = 1 << 30;
    const dim3 gGates((BSZ * HID / 4) / 256);

    // [0][1] fp32->tf32 conversions in two launches
    {
        const int n0 = BSZ * 2 * 1024, n1 = 2048 * 1024;
        const int n2 = G3H * OUTD,     n3 = OUTD * HID;
        int tA = n0 + n1 + n2 + n3;
        conv4<<<(tA + 255) / 256, 256>>>(
            x, xr, n0, (const float*)d_in[1], eW, n1,
            (const float*)d_in[3], i0, n2, (const float*)d_in[11], oW, n3);

        const int m0 = G3H * HID;
        int tB = 3 * m0;
        conv4<<<(tB + 255) / 256, 256>>>(
            (const float*)d_in[4], r0, m0, (const float*)d_in[7], i1, m0,
            (const float*)d_in[8], r1, m0, (const float*)d_in[8], r1, 0);
    }

    // [2] Embedding: M=1024 (b*2+l), N=2048, K=1024 -> relu -> h0/h1 + rounded
    gemm_tf32<2><<<dim3(2048 / TN, 1024 / TM), 256, SMEM_BYTES>>>(
        xr, 1024, eW, 1024, 1024,
        xr, 1024, eW, 1024, 1024,
        BIG, nullptr, 0, embB);

    // [3..] 2 warmup steps (zero input: gx0 skipped, gates use bias only)
    for (int w = 0; w < 2; w++) {
        gemm_tf32<0><<<dim3(G3H / TN, BSZ / TM), 256, SMEM_BYTES>>>(     // gh0
            h0r, HID, r0, HID, HID,
            h0r, HID, r0, HID, HID,
            BIG, g + G3H, GLD, nullptr);
        gru_gates<<<gGates, 256>>>(g, bih0, bhh0, h0, h0r, 0);

        // launch index 5 on w==0: main-loop-sized GEMM (for ncu -s 5 -c 1)
        gemm_tf32<0><<<dim3(GLD / TN, BSZ / TM), 256, SMEM_BYTES>>>(     // gx1|gh1
            h0r, HID, i1, HID, HID,
            h1r, HID, r1, HID, HID,
            G3H, g, GLD, nullptr);
        gru_gates<<<gGates, 256>>>(g, bih1, bhh1, h1, h1r, 1);
    }

    // out0 (split-K) -> preds[:,0,:] + rounded feedback
    gemm_tf32<3><<<dim3(OUTD / TN, BSZ / TM, KSPLIT), 256, SMEM_BYTES>>>(
        h1r, HID, oW, HID, HID / KSPLIT,
        h1r, HID, oW, HID, HID / KSPLIT,
        BIG, part, OUTD, nullptr);
    out_reduce<<<(BSZ * OUTD / 4) / 256, 256>>>(outB, out);

    // Feedback steps t = 1..31
    for (int t = 1; t < 32; t++) {
        gemm_tf32<0><<<dim3(GLD / TN, BSZ / TM), 256, SMEM_BYTES>>>(     // gx0|gh0
            outr, OUTD, i0, OUTD, OUTD,
            h0r,  HID,  r0, HID,  HID,
            G3H, g, GLD, nullptr);
        gru_gates<<<gGates, 256>>>(g, bih0, bhh0, h0, h0r, 1);

        gemm_tf32<0><<<dim3(GLD / TN, BSZ / TM), 256, SMEM_BYTES>>>(     // gx1|gh1
            h0r, HID, i1, HID, HID,
            h1r, HID, r1, HID, HID,
            G3H, g, GLD, nullptr);
        gru_gates<<<gGates, 256>>>(g, bih1, bhh1, h1, h1r, 1);

        gemm_tf32<3><<<dim3(OUTD / TN, BSZ / TM, KSPLIT), 256, SMEM_BYTES>>>(
            h1r, HID, oW, HID, HID / KSPLIT,
            h1r, HID, oW, HID, HID / KSPLIT,
            BIG, part, OUTD, nullptr);
        out_reduce<<<(BSZ * OUTD / 4) / 256, 256>>>(outB, out + (size_t)t * OUTD);
    }
}

// round 11
// speedup vs baseline: 1.2354x; 1.2354x over previous
#include <cuda_runtime.h>
#include <cstdint>

// ---------------------------------------------------------------------------
// _LSTMOneMany_3289944948986 : 2-layer GRU decoder, B=512, H=2048, O=512, T=32.
// tf32 mma.sync GEMMs (tcgen05 unavailable: harness targets sm_103 family).
// Round 11 (= Round 10 resubmit after broker failure): 128x128 CTA tile,
// 128 threads, 4 warps of 64x64 -> 16 FLOP/B of smem traffic (2x crossbar
// slack; 32x32 warp tiles had zero). R5 swizzled 32-stride layout (96KB/CTA,
// 2 CTAs/SM proven) + LDSM fragment loads. R5 loop structure.
// ---------------------------------------------------------------------------

#define BSZ   512
#define HID   2048
#define OUTD  512
#define G3H   6144
#define GLD   12288
#define KSPLIT 8
#define TM    128
#define TN    128

// ---- scratch (__device__ globals; no allocation allowed) ----
__device__ __align__(16) float g_g   [BSZ * GLD];     // gate pre-activations
__device__ __align__(16) float g_h0  [BSZ * HID];     // exact fp32 state
__device__ __align__(16) float g_h1  [BSZ * HID];
__device__ __align__(16) float g_h0r [BSZ * HID];     // tf32-rounded GEMM copies
__device__ __align__(16) float g_h1r [BSZ * HID];
__device__ __align__(16) float g_outr[BSZ * OUTD];    // rounded feedback input
__device__ __align__(16) float g_part[KSPLIT * BSZ * OUTD];

// tf32-rounded weights / inputs
__device__ __align__(16) float w_x   [BSZ * 2 * 1024];
__device__ __align__(16) float w_emb [2048 * 1024];
__device__ __align__(16) float w_ih0 [G3H * OUTD];
__device__ __align__(16) float w_hh0 [G3H * HID];
__device__ __align__(16) float w_ih1 [G3H * HID];
__device__ __align__(16) float w_hh1 [G3H * HID];
__device__ __align__(16) float w_out [OUTD * HID];

// ---------------------------------------------------------------------------
__device__ __forceinline__ float roundtf(float x) {
    uint32_t u;
    asm("cvt.rna.tf32.f32 %0, %1;" : "=r"(u) : "f"(x));
    return __uint_as_float(u);
}

// ---------------------------------------------------------------------------
// GEMM: C[M,N] = A[M,K] @ B[N,K]^T, operands already tf32-rounded fp32.
// 128x128 CTA tile, 128 threads (4 warps, 2x2 grid of 64x64 warp tiles),
// 3-stage cp.async. Smem tiles [128r][32c] with 16B-chunk XOR swizzle
// (chunk ^= row&7): conflict-free for both cp.async writes and LDSM reads.
// MODE 0: raw store.  MODE 2: embedding (bias+relu, scatter h0/h1 + rounded).
// MODE 3: split-K partial (blockIdx.z slice of K) into g_part.
// ---------------------------------------------------------------------------
#define STAGE_FLTS (2 * 128 * 32)                  // 8192 floats
#define STAGE_BYTES (STAGE_FLTS * 4)               // 32768
static const int SMEM_BYTES = 3 * STAGE_BYTES;     // 98304

template <int MODE>
__global__ void __launch_bounds__(128, 2)
gemm_tf32(const float* __restrict__ A0, int lda0,
          const float* __restrict__ B0, int ldb0, int K0,
          const float* __restrict__ A1, int lda1,
          const float* __restrict__ B1, int ldb1, int K1,
          int nSplit,
          float* __restrict__ C, int ldc,
          const float* __restrict__ bias)
{
    extern __shared__ float smem[];   // [3][A 128x32 | B 128x32] swizzled

    const int tid = threadIdx.x;
    const int bn  = blockIdx.x;
    const int bm  = blockIdx.y;
    const int nBase = bn * TN;

    const float* A; const float* B; int lda, ldb, K;
    if (nBase < nSplit) {
        A = A0; lda = lda0; B = B0 + (size_t)nBase * ldb0; ldb = ldb0; K = K0;
    } else {
        A = A1; lda = lda1; B = B1 + (size_t)(nBase - nSplit) * ldb1; ldb = ldb1; K = K1;
    }
    A += (size_t)bm * TM * lda;
    if (MODE == 3) {
        int koff = blockIdx.z * K;
        A += koff; B += koff;
        C += (size_t)blockIdx.z * (BSZ * OUTD);
    }

    const int lane = tid & 31;
    const int warp = tid >> 5;           // 0..3
    const int wm = (warp >> 1) << 6;     // 0 / 64
    const int wn = (warp & 1) << 6;      // 0 / 64
    const int lr = lane >> 2;            // 0..7
    const int lc = lane & 3;             // 0..3

    // ldmatrix lane roles
    const int lrow = lane & 7;
    const int lhlf = (lane >> 3) & 1;    // +8 rows
    const int lcol = (lane >> 4) & 1;    // +1 k-chunk (4 floats)

    // Per-site swizzled row constants (byte offsets within a stage).
    uint32_t aRowB[4], bRowB[4];
    int aSw[4], bSw[4];
#pragma unroll
    for (int i = 0; i < 4; i++) {
        int ar = wm + i * 16 + lrow + lhlf * 8;
        aRowB[i] = (uint32_t)(ar * 128);
        aSw[i]   = ar & 7;
        int br = wn + i * 16 + lrow + lhlf * 8;
        bRowB[i] = (uint32_t)(128 * 128 + br * 128);
        bSw[i]   = br & 7;
    }
    const uint32_t smemBase = (uint32_t)__cvta_generic_to_shared(smem);

    float acc[4][8][4];
#pragma unroll
    for (int i = 0; i < 4; i++)
#pragma unroll
        for (int j = 0; j < 8; j++)
#pragma unroll
            for (int k = 0; k < 4; k++) acc[i][j][k] = 0.f;

    auto load_stage = [&](int buf, int k0) {
        float* sA = smem + buf * STAGE_FLTS;
        float* sB = sA + 128 * 32;
        const int tRow = tid >> 3;      // 0..15
        const int tCh  = tid & 7;       // 0..7
#pragma unroll
        for (int p = 0; p < 8; p++) {
            int row = tRow + p * 16;
            int dst = row * 32 + ((tCh ^ (row & 7)) << 2);
            uint32_t da = (uint32_t)__cvta_generic_to_shared(&sA[dst]);
            uint32_t db = (uint32_t)__cvta_generic_to_shared(&sB[dst]);
            asm volatile("cp.async.cg.shared.global [%0], [%1], 16;\n"
                         :: "r"(da), "l"(A + (size_t)row * lda + k0 + tCh * 4));
            asm volatile("cp.async.cg.shared.global [%0], [%1], 16;\n"
                         :: "r"(db), "l"(B + (size_t)row * ldb + k0 + tCh * 4));
        }
        asm volatile("cp.async.commit_group;\n");
    };

    const int nStages = K >> 5;        // K multiple of 64 everywhere -> >= 2
    load_stage(0, 0);
    if (nStages > 1) load_stage(1, 32);
    int buf = 0;

    for (int st = 0; st < nStages; st++) {
        if (st + 2 < nStages) {
            load_stage((st + 2) % 3, (st + 2) * 32);
            asm volatile("cp.async.wait_group 2;\n");
        } else if (st + 1 < nStages) {
            asm volatile("cp.async.wait_group 1;\n");
        } else {
            asm volatile("cp.async.wait_group 0;\n");
        }
        __syncthreads();

        const uint32_t stBase = smemBase + (uint32_t)(buf * STAGE_BYTES);

#pragma unroll
        for (int kk = 0; kk < 4; kk++) {
            const int kch = kk * 2 + lcol;           // this lane's k-chunk
            uint32_t af[4][4], bf[8][2];
#pragma unroll
            for (int mt = 0; mt < 4; mt++) {
                uint32_t ad = stBase + aRowB[mt] + (uint32_t)(((kch ^ aSw[mt]) << 4));
                asm volatile(
                    "ldmatrix.sync.aligned.m8n8.x4.shared.b16 {%0,%1,%2,%3}, [%4];\n"
                    : "=r"(af[mt][0]), "=r"(af[mt][1]),
                      "=r"(af[mt][2]), "=r"(af[mt][3])
                    : "r"(ad));
            }
#pragma unroll
            for (int n4 = 0; n4 < 4; n4++) {
                uint32_t bd = stBase + bRowB[n4] + (uint32_t)(((kch ^ bSw[n4]) << 4));
                asm volatile(
                    "ldmatrix.sync.aligned.m8n8.x4.shared.b16 {%0,%1,%2,%3}, [%4];\n"
                    : "=r"(bf[2 * n4][0]), "=r"(bf[2 * n4 + 1][0]),
                      "=r"(bf[2 * n4][1]), "=r"(bf[2 * n4 + 1][1])
                    : "r"(bd));
            }
#pragma unroll
            for (int mt = 0; mt < 4; mt++)
#pragma unroll
                for (int nt = 0; nt < 8; nt++) {
                    float* c = acc[mt][nt];
                    asm volatile(
                        "mma.sync.aligned.m16n8k8.row.col.f32.tf32.tf32.f32 "
                        "{%0,%1,%2,%3}, {%4,%5,%6,%7}, {%8,%9}, {%0,%1,%2,%3};\n"
                        : "+f"(c[0]), "+f"(c[1]), "+f"(c[2]), "+f"(c[3])
                        : "r"(af[mt][0]), "r"(af[mt][1]), "r"(af[mt][2]), "r"(af[mt][3]),
                          "r"(bf[nt][0]), "r"(bf[nt][1]));
                }
        }
        __syncthreads();
        buf = (buf + 1) % 3;
    }

    // -------- epilogue --------
#pragma unroll
    for (int mt = 0; mt < 4; mt++)
#pragma unroll
        for (int nt = 0; nt < 8; nt++) {
            int m = bm * TM + wm + mt * 16 + lr;
            int n = nBase + wn + nt * 8 + lc * 2;
            float2 v0 = make_float2(acc[mt][nt][0], acc[mt][nt][1]);
            float2 v1 = make_float2(acc[mt][nt][2], acc[mt][nt][3]);
            if (MODE == 0 || MODE == 3) {
                *(float2*)&C[(size_t)m       * ldc + n] = v0;
                *(float2*)&C[(size_t)(m + 8) * ldc + n] = v1;
            } else {  // MODE 2: embedding -> relu; scatter to h0/h1 (+ rounded)
                float b0 = bias[n], b1 = bias[n + 1];
                v0.x = fmaxf(v0.x + b0, 0.f); v0.y = fmaxf(v0.y + b1, 0.f);
                v1.x = fmaxf(v1.x + b0, 0.f); v1.y = fmaxf(v1.y + b1, 0.f);
                float* hp = (m & 1) ? g_h1  : g_h0;
                float* hr = (m & 1) ? g_h1r : g_h0r;
                size_t o0 = (size_t)(m >> 1) * HID + n;
                size_t o1 = o0 + 4 * HID;              // rows m, m+8 same parity
                *(float2*)&hp[o0] = v0;
                *(float2*)&hp[o1] = v1;
                *(float2*)&hr[o0] = make_float2(roundtf(v0.x), roundtf(v0.y));
                *(float2*)&hr[o1] = make_float2(roundtf(v1.x), roundtf(v1.y));
            }
        }
}

// ---------------------------------------------------------------------------
// GRU gates (float4): r=sig(gx_r+gh_r), z=sig(gx_z+gh_z), n=tanh(gx_n+r*gh_n),
//                     h = (1-z)*n + z*h.  Writes exact fp32 h + rounded copy.
// ---------------------------------------------------------------------------
__global__ void __launch_bounds__(256)
gru_gates(const float* __restrict__ g,
          const float* __restrict__ bih, const float* __restrict__ bhh,
          float* __restrict__ h, float* __restrict__ hr, int hasGx)
{
    int idx = (blockIdx.x * 256 + threadIdx.x) * 4;   // < 512*2048
    int b = idx >> 11, j = idx & 2047;
    const float* gb = g + (size_t)b * GLD;

    float4 gxr = *(const float4*)&bih[j];
    float4 gxz = *(const float4*)&bih[HID + j];
    float4 gxn = *(const float4*)&bih[2 * HID + j];
    if (hasGx) {
        float4 a = *(const float4*)&gb[j];
        float4 c = *(const float4*)&gb[HID + j];
        float4 d = *(const float4*)&gb[2 * HID + j];
        gxr.x += a.x; gxr.y += a.y; gxr.z += a.z; gxr.w += a.w;
        gxz.x += c.x; gxz.y += c.y; gxz.z += c.z; gxz.w += c.w;
        gxn.x += d.x; gxn.y += d.y; gxn.z += d.z; gxn.w += d.w;
    }
    float4 ghr = *(const float4*)&gb[G3H + j];
    float4 ghz = *(const float4*)&gb[G3H + HID + j];
    float4 ghn = *(const float4*)&gb[G3H + 2 * HID + j];
    float4 br  = *(const float4*)&bhh[j];
    float4 bz  = *(const float4*)&bhh[HID + j];
    float4 bn  = *(const float4*)&bhh[2 * HID + j];
    float4 hp  = *(const float4*)&h[idx];

    float4 ho, hro;
#pragma unroll
    for (int q = 0; q < 4; q++) {
        float xr = ((float*)&gxr)[q], xz = ((float*)&gxz)[q], xn = ((float*)&gxn)[q];
        float vr = ((float*)&ghr)[q] + ((float*)&br)[q];
        float vz = ((float*)&ghz)[q] + ((float*)&bz)[q];
        float vn = ((float*)&ghn)[q] + ((float*)&bn)[q];
        float r = 1.f / (1.f + expf(-(xr + vr)));
        float z = 1.f / (1.f + expf(-(xz + vz)));
        float n = tanhf(xn + r * vn);
        float hv = (1.f - z) * n + z * ((float*)&hp)[q];
        ((float*)&ho)[q]  = hv;
        ((float*)&hro)[q] = roundtf(hv);
    }
    *(float4*)&h[idx]  = ho;
    *(float4*)&hr[idx] = hro;
}

// Reduce split-K partials + bias -> exact preds slice + rounded feedback buf.
__global__ void __launch_bounds__(256)
out_reduce(const float* __restrict__ outB, float* __restrict__ preds)
{
    int idx = (blockIdx.x * 256 + threadIdx.x) * 4;   // < 512*512
    int o = idx & 511, b = idx >> 9;
    float4 v = *(const float4*)&outB[o];
#pragma unroll
    for (int z = 0; z < KSPLIT; z++) {
        float4 pz = *(const float4*)&g_part[z * (BSZ * OUTD) + idx];
        v.x += pz.x; v.y += pz.y; v.z += pz.z; v.w += pz.w;
    }
    *(float4*)&preds[(size_t)b * (32 * OUTD) + o] = v;
    *(float4*)&g_outr[idx] =
        make_float4(roundtf(v.x), roundtf(v.y), roundtf(v.z), roundtf(v.w));
}

// fp32 -> tf32-rounded fp32, 4 segments per launch
__global__ void __launch_bounds__(256)
conv4(const float* s0, float* d0, int n0, const float* s1, float* d1, int n1,
      const float* s2, float* d2, int n2, const float* s3, float* d3, int n3)
{
    int i = blockIdx.x * 256 + threadIdx.x;
    if      (i < n0)         d0[i] = roundtf(s0[i]);
    else if ((i -= n0) < n1) d1[i] = roundtf(s1[i]);
    else if ((i -= n1) < n2) d2[i] = roundtf(s2[i]);
    else if ((i -= n2) < n3) d3[i] = roundtf(s3[i]);
}

// ---------------------------------------------------------------------------

extern "C" void kernel_launch(void* const* d_in, const int* in_sizes, int n_in,
                              void* d_out, int out_size)
{
    const float* x    = (const float*)d_in[0];
    const float* embB = (const float*)d_in[2];
    const float* bih0 = (const float*)d_in[5];
    const float* bhh0 = (const float*)d_in[6];
    const float* bih1 = (const float*)d_in[9];
    const float* bhh1 = (const float*)d_in[10];
    const float* outB = (const float*)d_in[12];
    float* out = (float*)d_out;                  // [512, 32, 512]

    cudaFuncSetAttribute(gemm_tf32<0>,
                         cudaFuncAttributeMaxDynamicSharedMemorySize, SMEM_BYTES);
    cudaFuncSetAttribute(gemm_tf32<2>,
                         cudaFuncAttributeMaxDynamicSharedMemorySize, SMEM_BYTES);
    cudaFuncSetAttribute(gemm_tf32<3>,
                         cudaFuncAttributeMaxDynamicSharedMemorySize, SMEM_BYTES);

    void* p;
    cudaGetSymbolAddress(&p, g_g);    float* g    = (float*)p;
    cudaGetSymbolAddress(&p, g_h0);   float* h0   = (float*)p;
    cudaGetSymbolAddress(&p, g_h1);   float* h1   = (float*)p;
    cudaGetSymbolAddress(&p, g_h0r);  float* h0r  = (float*)p;
    cudaGetSymbolAddress(&p, g_h1r);  float* h1r  = (float*)p;
    cudaGetSymbolAddress(&p, g_outr); float* outr = (float*)p;
    cudaGetSymbolAddress(&p, g_part); float* part = (float*)p;
    cudaGetSymbolAddress(&p, w_x);    float* xr   = (float*)p;
    cudaGetSymbolAddress(&p, w_emb);  float* eW   = (float*)p;
    cudaGetSymbolAddress(&p, w_ih0);  float* i0   = (float*)p;
    cudaGetSymbolAddress(&p, w_hh0);  float* r0   = (float*)p;
    cudaGetSymbolAddress(&p, w_ih1);  float* i1   = (float*)p;
    cudaGetSymbolAddress(&p, w_hh1);  float* r1   = (float*)p;
    cudaGetSymbolAddress(&p, w_out);  float* oW   = (float*)p;

    const int BIG = 1 << 30;
    const dim3 gGates((BSZ * HID / 4) / 256);

    // [0][1] fp32->tf32 conversions in two launches
    {
        const int n0 = BSZ * 2 * 1024, n1 = 2048 * 1024;
        const int n2 = G3H * OUTD,     n3 = OUTD * HID;
        int tA = n0 + n1 + n2 + n3;
        conv4<<<(tA + 255) / 256, 256>>>(
            x, xr, n0, (const float*)d_in[1], eW, n1,
            (const float*)d_in[3], i0, n2, (const float*)d_in[11], oW, n3);

        const int m0 = G3H * HID;
        int tB = 3 * m0;
        conv4<<<(tB + 255) / 256, 256>>>(
            (const float*)d_in[4], r0, m0, (const float*)d_in[7], i1, m0,
            (const float*)d_in[8], r1, m0, (const float*)d_in[8], r1, 0);
    }

    // [2] Embedding: M=1024 (b*2+l), N=2048, K=1024 -> relu -> h0/h1 + rounded
    gemm_tf32<2><<<dim3(2048 / TN, 1024 / TM), 128, SMEM_BYTES>>>(
        xr, 1024, eW, 1024, 1024,
        xr, 1024, eW, 1024, 1024,
        BIG, nullptr, 0, embB);

    // [3..] 2 warmup steps (zero input: gx0 skipped, gates use bias only)
    for (int w = 0; w < 2; w++) {
        gemm_tf32<0><<<dim3(G3H / TN, BSZ / TM), 128, SMEM_BYTES>>>(     // gh0
            h0r, HID, r0, HID, HID,
            h0r, HID, r0, HID, HID,
            BIG, g + G3H, GLD, nullptr);
        gru_gates<<<gGates, 256>>>(g, bih0, bhh0, h0, h0r, 0);

        // launch index 5 on w==0: main-loop-sized GEMM (for ncu -s 5 -c 1)
        gemm_tf32<0><<<dim3(GLD / TN, BSZ / TM), 128, SMEM_BYTES>>>(     // gx1|gh1
            h0r, HID, i1, HID, HID,
            h1r, HID, r1, HID, HID,
            G3H, g, GLD, nullptr);
        gru_gates<<<gGates, 256>>>(g, bih1, bhh1, h1, h1r, 1);
    }

    // out0 (split-K) -> preds[:,0,:] + rounded feedback
    gemm_tf32<3><<<dim3(OUTD / TN, BSZ / TM, KSPLIT), 128, SMEM_BYTES>>>(
        h1r, HID, oW, HID, HID / KSPLIT,
        h1r, HID, oW, HID, HID / KSPLIT,
        BIG, part, OUTD, nullptr);
    out_reduce<<<(BSZ * OUTD / 4) / 256, 256>>>(outB, out);

    // Feedback steps t = 1..31
    for (int t = 1; t < 32; t++) {
        gemm_tf32<0><<<dim3(GLD / TN, BSZ / TM), 128, SMEM_BYTES>>>(     // gx0|gh0
            outr, OUTD, i0, OUTD, OUTD,
            h0r,  HID,  r0, HID,  HID,
            G3H, g, GLD, nullptr);
        gru_gates<<<gGates, 256>>>(g, bih0, bhh0, h0, h0r, 1);

        gemm_tf32<0><<<dim3(GLD / TN, BSZ / TM), 128, SMEM_BYTES>>>(     // gx1|gh1
            h0r, HID, i1, HID, HID,
            h1r, HID, r1, HID, HID,
            G3H, g, GLD, nullptr);
        gru_gates<<<gGates, 256>>>(g, bih1, bhh1, h1, h1r, 1);

        gemm_tf32<3><<<dim3(OUTD / TN, BSZ / TM, KSPLIT), 128, SMEM_BYTES>>>(
            h1r, HID, oW, HID, HID / KSPLIT,
            h1r, HID, oW, HID, HID / KSPLIT,
            BIG, part, OUTD, nullptr);
        out_reduce<<<(BSZ * OUTD / 4) / 256, 256>>>(outB, out + (size_t)t * OUTD);
    }
}

// round 12
// speedup vs baseline: 1.2530x; 1.0142x over previous
#include <cuda_runtime.h>
#include <cstdint>

// ---------------------------------------------------------------------------
// _LSTMOneMany_3289944948986 : 2-layer GRU decoder, B=512, H=2048, O=512, T=32.
// tf32 mma.sync GEMMs (tcgen05 unavailable: harness targets sm_103 family).
// Round 12: split-K=2 on the recurrent GEMMs -> 768 fine-grained CTAs per
// launch (kills the 65% wave-balance loss + gx/gh duration mismatch seen in
// R11 ncu). Two g-planes summed in the gate kernel. R11 GEMM core unchanged
// (128x128 CTA, 4 warps of 64x64, LDSM, swizzled 3-stage cp.async).
// ---------------------------------------------------------------------------

#define BSZ   512
#define HID   2048
#define OUTD  512
#define G3H   6144
#define GLD   12288
#define PLANE (BSZ * GLD)
#define KSPLIT 8
#define TM    128
#define TN    128

// ---- scratch (__device__ globals; no allocation allowed) ----
__device__ __align__(16) float g_g   [2 * PLANE];     // gate pre-acts, 2 K-planes
__device__ __align__(16) float g_h0  [BSZ * HID];     // exact fp32 state
__device__ __align__(16) float g_h1  [BSZ * HID];
__device__ __align__(16) float g_h0r [BSZ * HID];     // tf32-rounded GEMM copies
__device__ __align__(16) float g_h1r [BSZ * HID];
__device__ __align__(16) float g_outr[BSZ * OUTD];    // rounded feedback input
__device__ __align__(16) float g_part[KSPLIT * BSZ * OUTD];

// tf32-rounded weights / inputs
__device__ __align__(16) float w_x   [BSZ * 2 * 1024];
__device__ __align__(16) float w_emb [2048 * 1024];
__device__ __align__(16) float w_ih0 [G3H * OUTD];
__device__ __align__(16) float w_hh0 [G3H * HID];
__device__ __align__(16) float w_ih1 [G3H * HID];
__device__ __align__(16) float w_hh1 [G3H * HID];
__device__ __align__(16) float w_out [OUTD * HID];

// ---------------------------------------------------------------------------
__device__ __forceinline__ float roundtf(float x) {
    uint32_t u;
    asm("cvt.rna.tf32.f32 %0, %1;" : "=r"(u) : "f"(x));
    return __uint_as_float(u);
}

// ---------------------------------------------------------------------------
// GEMM: C[M,N] = A[M,K] @ B[N,K]^T, operands already tf32-rounded fp32.
// 128x128 CTA tile, 128 threads (4 warps, 2x2 grid of 64x64 warp tiles),
// 3-stage cp.async, swizzled smem, LDSM fragment loads.
// nSplit selects per-N-block source; K0/K1 are PER-Z-SLICE depths.
// MODE 2: embedding (bias+relu, scatter h0/h1 + rounded), no z logic.
// MODE 3: z-sliced: koff = z*K, C += z*cStrideZ (split-K partial planes).
// ---------------------------------------------------------------------------
#define STAGE_FLTS (2 * 128 * 32)                  // 8192 floats
#define STAGE_BYTES (STAGE_FLTS * 4)               // 32768
static const int SMEM_BYTES = 3 * STAGE_BYTES;     // 98304

template <int MODE>
__global__ void __launch_bounds__(128, 2)
gemm_tf32(const float* __restrict__ A0, int lda0,
          const float* __restrict__ B0, int ldb0, int K0,
          const float* __restrict__ A1, int lda1,
          const float* __restrict__ B1, int ldb1, int K1,
          int nSplit,
          float* __restrict__ C, int ldc, int cStrideZ,
          const float* __restrict__ bias)
{
    extern __shared__ float smem[];   // [3][A 128x32 | B 128x32] swizzled

    const int tid = threadIdx.x;
    const int bn  = blockIdx.x;
    const int bm  = blockIdx.y;
    const int nBase = bn * TN;

    const float* A; const float* B; int lda, ldb, K;
    if (nBase < nSplit) {
        A = A0; lda = lda0; B = B0 + (size_t)nBase * ldb0; ldb = ldb0; K = K0;
    } else {
        A = A1; lda = lda1; B = B1 + (size_t)(nBase - nSplit) * ldb1; ldb = ldb1; K = K1;
    }
    A += (size_t)bm * TM * lda;
    if (MODE == 3) {
        int koff = blockIdx.z * K;     // K is the per-slice depth
        A += koff; B += koff;
        C += (size_t)blockIdx.z * (size_t)cStrideZ;
    }

    const int lane = tid & 31;
    const int warp = tid >> 5;           // 0..3
    const int wm = (warp >> 1) << 6;     // 0 / 64
    const int wn = (warp & 1) << 6;      // 0 / 64
    const int lr = lane >> 2;            // 0..7
    const int lc = lane & 3;             // 0..3

    // ldmatrix lane roles
    const int lrow = lane & 7;
    const int lhlf = (lane >> 3) & 1;    // +8 rows
    const int lcol = (lane >> 4) & 1;    // +1 k-chunk (4 floats)

    // Per-site swizzled row constants (byte offsets within a stage).
    uint32_t aRowB[4], bRowB[4];
    int aSw[4], bSw[4];
#pragma unroll
    for (int i = 0; i < 4; i++) {
        int ar = wm + i * 16 + lrow + lhlf * 8;
        aRowB[i] = (uint32_t)(ar * 128);
        aSw[i]   = ar & 7;
        int br = wn + i * 16 + lrow + lhlf * 8;
        bRowB[i] = (uint32_t)(128 * 128 + br * 128);
        bSw[i]   = br & 7;
    }
    const uint32_t smemBase = (uint32_t)__cvta_generic_to_shared(smem);

    float acc[4][8][4];
#pragma unroll
    for (int i = 0; i < 4; i++)
#pragma unroll
        for (int j = 0; j < 8; j++)
#pragma unroll
            for (int k = 0; k < 4; k++) acc[i][j][k] = 0.f;

    auto load_stage = [&](int buf, int k0) {
        float* sA = smem + buf * STAGE_FLTS;
        float* sB = sA + 128 * 32;
        const int tRow = tid >> 3;      // 0..15
        const int tCh  = tid & 7;       // 0..7
#pragma unroll
        for (int p = 0; p < 8; p++) {
            int row = tRow + p * 16;
            int dst = row * 32 + ((tCh ^ (row & 7)) << 2);
            uint32_t da = (uint32_t)__cvta_generic_to_shared(&sA[dst]);
            uint32_t db = (uint32_t)__cvta_generic_to_shared(&sB[dst]);
            asm volatile("cp.async.cg.shared.global [%0], [%1], 16;\n"
                         :: "r"(da), "l"(A + (size_t)row * lda + k0 + tCh * 4));
            asm volatile("cp.async.cg.shared.global [%0], [%1], 16;\n"
                         :: "r"(db), "l"(B + (size_t)row * ldb + k0 + tCh * 4));
        }
        asm volatile("cp.async.commit_group;\n");
    };

    const int nStages = K >> 5;        // K multiple of 64 everywhere -> >= 2
    load_stage(0, 0);
    if (nStages > 1) load_stage(1, 32);
    int buf = 0;

    for (int st = 0; st < nStages; st++) {
        if (st + 2 < nStages) {
            load_stage((st + 2) % 3, (st + 2) * 32);
            asm volatile("cp.async.wait_group 2;\n");
        } else if (st + 1 < nStages) {
            asm volatile("cp.async.wait_group 1;\n");
        } else {
            asm volatile("cp.async.wait_group 0;\n");
        }
        __syncthreads();

        const uint32_t stBase = smemBase + (uint32_t)(buf * STAGE_BYTES);

#pragma unroll
        for (int kk = 0; kk < 4; kk++) {
            const int kch = kk * 2 + lcol;           // this lane's k-chunk
            uint32_t af[4][4], bf[8][2];
#pragma unroll
            for (int mt = 0; mt < 4; mt++) {
                uint32_t ad = stBase + aRowB[mt] + (uint32_t)(((kch ^ aSw[mt]) << 4));
                asm volatile(
                    "ldmatrix.sync.aligned.m8n8.x4.shared.b16 {%0,%1,%2,%3}, [%4];\n"
                    : "=r"(af[mt][0]), "=r"(af[mt][1]),
                      "=r"(af[mt][2]), "=r"(af[mt][3])
                    : "r"(ad));
            }
#pragma unroll
            for (int n4 = 0; n4 < 4; n4++) {
                uint32_t bd = stBase + bRowB[n4] + (uint32_t)(((kch ^ bSw[n4]) << 4));
                asm volatile(
                    "ldmatrix.sync.aligned.m8n8.x4.shared.b16 {%0,%1,%2,%3}, [%4];\n"
                    : "=r"(bf[2 * n4][0]), "=r"(bf[2 * n4 + 1][0]),
                      "=r"(bf[2 * n4][1]), "=r"(bf[2 * n4 + 1][1])
                    : "r"(bd));
            }
#pragma unroll
            for (int mt = 0; mt < 4; mt++)
#pragma unroll
                for (int nt = 0; nt < 8; nt++) {
                    float* c = acc[mt][nt];
                    asm volatile(
                        "mma.sync.aligned.m16n8k8.row.col.f32.tf32.tf32.f32 "
                        "{%0,%1,%2,%3}, {%4,%5,%6,%7}, {%8,%9}, {%0,%1,%2,%3};\n"
                        : "+f"(c[0]), "+f"(c[1]), "+f"(c[2]), "+f"(c[3])
                        : "r"(af[mt][0]), "r"(af[mt][1]), "r"(af[mt][2]), "r"(af[mt][3]),
                          "r"(bf[nt][0]), "r"(bf[nt][1]));
                }
        }
        __syncthreads();
        buf = (buf + 1) % 3;
    }

    // -------- epilogue --------
#pragma unroll
    for (int mt = 0; mt < 4; mt++)
#pragma unroll
        for (int nt = 0; nt < 8; nt++) {
            int m = bm * TM + wm + mt * 16 + lr;
            int n = nBase + wn + nt * 8 + lc * 2;
            float2 v0 = make_float2(acc[mt][nt][0], acc[mt][nt][1]);
            float2 v1 = make_float2(acc[mt][nt][2], acc[mt][nt][3]);
            if (MODE == 3) {
                *(float2*)&C[(size_t)m       * ldc + n] = v0;
                *(float2*)&C[(size_t)(m + 8) * ldc + n] = v1;
            } else {  // MODE 2: embedding -> relu; scatter to h0/h1 (+ rounded)
                float b0 = bias[n], b1 = bias[n + 1];
                v0.x = fmaxf(v0.x + b0, 0.f); v0.y = fmaxf(v0.y + b1, 0.f);
                v1.x = fmaxf(v1.x + b0, 0.f); v1.y = fmaxf(v1.y + b1, 0.f);
                float* hp = (m & 1) ? g_h1  : g_h0;
                float* hr = (m & 1) ? g_h1r : g_h0r;
                size_t o0 = (size_t)(m >> 1) * HID + n;
                size_t o1 = o0 + 4 * HID;              // rows m, m+8 same parity
                *(float2*)&hp[o0] = v0;
                *(float2*)&hp[o1] = v1;
                *(float2*)&hr[o0] = make_float2(roundtf(v0.x), roundtf(v0.y));
                *(float2*)&hr[o1] = make_float2(roundtf(v1.x), roundtf(v1.y));
            }
        }
}

// ---------------------------------------------------------------------------
// GRU gates (float4): sums the two split-K planes of g, then
// r=sig(gx_r+gh_r), z=sig(gx_z+gh_z), n=tanh(gx_n+r*gh_n), h=(1-z)n+z*h.
// ---------------------------------------------------------------------------
__global__ void __launch_bounds__(256)
gru_gates(const float* __restrict__ g,
          const float* __restrict__ bih, const float* __restrict__ bhh,
          float* __restrict__ h, float* __restrict__ hr, int hasGx)
{
    int idx = (blockIdx.x * 256 + threadIdx.x) * 4;   // < 512*2048
    int b = idx >> 11, j = idx & 2047;
    const float* g0 = g + (size_t)b * GLD;
    const float* g1 = g0 + PLANE;

    float4 gxr = *(const float4*)&bih[j];
    float4 gxz = *(const float4*)&bih[HID + j];
    float4 gxn = *(const float4*)&bih[2 * HID + j];
    if (hasGx) {
#pragma unroll
        for (int pl = 0; pl < 2; pl++) {
            const float* gp = pl ? g1 : g0;
            float4 a = *(const float4*)&gp[j];
            float4 c = *(const float4*)&gp[HID + j];
            float4 d = *(const float4*)&gp[2 * HID + j];
            gxr.x += a.x; gxr.y += a.y; gxr.z += a.z; gxr.w += a.w;
            gxz.x += c.x; gxz.y += c.y; gxz.z += c.z; gxz.w += c.w;
            gxn.x += d.x; gxn.y += d.y; gxn.z += d.z; gxn.w += d.w;
        }
    }
    float4 ghr = *(const float4*)&bhh[j];
    float4 ghz = *(const float4*)&bhh[HID + j];
    float4 ghn = *(const float4*)&bhh[2 * HID + j];
#pragma unroll
    for (int pl = 0; pl < 2; pl++) {
        const float* gp = pl ? g1 : g0;
        float4 a = *(const float4*)&gp[G3H + j];
        float4 c = *(const float4*)&gp[G3H + HID + j];
        float4 d = *(const float4*)&gp[G3H + 2 * HID + j];
        ghr.x += a.x; ghr.y += a.y; ghr.z += a.z; ghr.w += a.w;
        ghz.x += c.x; ghz.y += c.y; ghz.z += c.z; ghz.w += c.w;
        ghn.x += d.x; ghn.y += d.y; ghn.z += d.z; ghn.w += d.w;
    }
    float4 hp = *(const float4*)&h[idx];

    float4 ho, hro;
#pragma unroll
    for (int q = 0; q < 4; q++) {
        float xr = ((float*)&gxr)[q], xz = ((float*)&gxz)[q], xn = ((float*)&gxn)[q];
        float vr = ((float*)&ghr)[q];
        float vz = ((float*)&ghz)[q];
        float vn = ((float*)&ghn)[q];
        float r = 1.f / (1.f + expf(-(xr + vr)));
        float z = 1.f / (1.f + expf(-(xz + vz)));
        float n = tanhf(xn + r * vn);
        float hv = (1.f - z) * n + z * ((float*)&hp)[q];
        ((float*)&ho)[q]  = hv;
        ((float*)&hro)[q] = roundtf(hv);
    }
    *(float4*)&h[idx]  = ho;
    *(float4*)&hr[idx] = hro;
}

// Reduce split-K partials + bias -> exact preds slice + rounded feedback buf.
__global__ void __launch_bounds__(256)
out_reduce(const float* __restrict__ outB, float* __restrict__ preds)
{
    int idx = (blockIdx.x * 256 + threadIdx.x) * 4;   // < 512*512
    int o = idx & 511, b = idx >> 9;
    float4 v = *(const float4*)&outB[o];
#pragma unroll
    for (int z = 0; z < KSPLIT; z++) {
        float4 pz = *(const float4*)&g_part[z * (BSZ * OUTD) + idx];
        v.x += pz.x; v.y += pz.y; v.z += pz.z; v.w += pz.w;
    }
    *(float4*)&preds[(size_t)b * (32 * OUTD) + o] = v;
    *(float4*)&g_outr[idx] =
        make_float4(roundtf(v.x), roundtf(v.y), roundtf(v.z), roundtf(v.w));
}

// fp32 -> tf32-rounded fp32, 4 segments per launch
__global__ void __launch_bounds__(256)
conv4(const float* s0, float* d0, int n0, const float* s1, float* d1, int n1,
      const float* s2, float* d2, int n2, const float* s3, float* d3, int n3)
{
    int i = blockIdx.x * 256 + threadIdx.x;
    if      (i < n0)         d0[i] = roundtf(s0[i]);
    else if ((i -= n0) < n1) d1[i] = roundtf(s1[i]);
    else if ((i -= n1) < n2) d2[i] = roundtf(s2[i]);
    else if ((i -= n2) < n3) d3[i] = roundtf(s3[i]);
}

// ---------------------------------------------------------------------------

extern "C" void kernel_launch(void* const* d_in, const int* in_sizes, int n_in,
                              void* d_out, int out_size)
{
    const float* x    = (const float*)d_in[0];
    const float* embB = (const float*)d_in[2];
    const float* bih0 = (const float*)d_in[5];
    const float* bhh0 = (const float*)d_in[6];
    const float* bih1 = (const float*)d_in[9];
    const float* bhh1 = (const float*)d_in[10];
    const float* outB = (const float*)d_in[12];
    float* out = (float*)d_out;                  // [512, 32, 512]

    cudaFuncSetAttribute(gemm_tf32<2>,
                         cudaFuncAttributeMaxDynamicSharedMemorySize, SMEM_BYTES);
    cudaFuncSetAttribute(gemm_tf32<3>,
                         cudaFuncAttributeMaxDynamicSharedMemorySize, SMEM_BYTES);

    void* p;
    cudaGetSymbolAddress(&p, g_g);    float* g    = (float*)p;
    cudaGetSymbolAddress(&p, g_h0);   float* h0   = (float*)p;
    cudaGetSymbolAddress(&p, g_h1);   float* h1   = (float*)p;
    cudaGetSymbolAddress(&p, g_h0r);  float* h0r  = (float*)p;
    cudaGetSymbolAddress(&p, g_h1r);  float* h1r  = (float*)p;
    cudaGetSymbolAddress(&p, g_outr); float* outr = (float*)p;
    cudaGetSymbolAddress(&p, g_part); float* part = (float*)p;
    cudaGetSymbolAddress(&p, w_x);    float* xr   = (float*)p;
    cudaGetSymbolAddress(&p, w_emb);  float* eW   = (float*)p;
    cudaGetSymbolAddress(&p, w_ih0);  float* i0   = (float*)p;
    cudaGetSymbolAddress(&p, w_hh0);  float* r0   = (float*)p;
    cudaGetSymbolAddress(&p, w_ih1);  float* i1   = (float*)p;
    cudaGetSymbolAddress(&p, w_hh1);  float* r1   = (float*)p;
    cudaGetSymbolAddress(&p, w_out);  float* oW   = (float*)p;

    const int BIG = 1 << 30;
    const dim3 gGates((BSZ * HID / 4) / 256);

    // [0][1] fp32->tf32 conversions in two launches
    {
        const int n0 = BSZ * 2 * 1024, n1 = 2048 * 1024;
        const int n2 = G3H * OUTD,     n3 = OUTD * HID;
        int tA = n0 + n1 + n2 + n3;
        conv4<<<(tA + 255) / 256, 256>>>(
            x, xr, n0, (const float*)d_in[1], eW, n1,
            (const float*)d_in[3], i0, n2, (const float*)d_in[11], oW, n3);

        const int m0 = G3H * HID;
        int tB = 3 * m0;
        conv4<<<(tB + 255) / 256, 256>>>(
            (const float*)d_in[4], r0, m0, (const float*)d_in[7], i1, m0,
            (const float*)d_in[8], r1, m0, (const float*)d_in[8], r1, 0);
    }

    // [2] Embedding: M=1024 (b*2+l), N=2048, K=1024 -> relu -> h0/h1 + rounded
    gemm_tf32<2><<<dim3(2048 / TN, 1024 / TM), 128, SMEM_BYTES>>>(
        xr, 1024, eW, 1024, 1024,
        xr, 1024, eW, 1024, 1024,
        BIG, nullptr, 0, 0, embB);

    // [3..] 2 warmup steps (zero input: gx0 skipped, gates use bias only)
    for (int w = 0; w < 2; w++) {
        // gh0, split-K=2: per-slice K=1024, planes at g / g+PLANE (col G3H)
        gemm_tf32<3><<<dim3(G3H / TN, BSZ / TM, 2), 128, SMEM_BYTES>>>(
            h0r, HID, r0, HID, 1024,
            h0r, HID, r0, HID, 1024,
            BIG, g + G3H, GLD, PLANE, nullptr);
        gru_gates<<<gGates, 256>>>(g, bih0, bhh0, h0, h0r, 0);

        // launch index 5 on w==0: main-loop-sized GEMM (for ncu -s 5 -c 1)
        gemm_tf32<3><<<dim3(GLD / TN, BSZ / TM, 2), 128, SMEM_BYTES>>>(  // gx1|gh1
            h0r, HID, i1, HID, 1024,
            h1r, HID, r1, HID, 1024,
            G3H, g, GLD, PLANE, nullptr);
        gru_gates<<<gGates, 256>>>(g, bih1, bhh1, h1, h1r, 1);
    }

    // out0 (split-K=8) -> preds[:,0,:] + rounded feedback
    gemm_tf32<3><<<dim3(OUTD / TN, BSZ / TM, KSPLIT), 128, SMEM_BYTES>>>(
        h1r, HID, oW, HID, HID / KSPLIT,
        h1r, HID, oW, HID, HID / KSPLIT,
        BIG, part, OUTD, BSZ * OUTD, nullptr);
    out_reduce<<<(BSZ * OUTD / 4) / 256, 256>>>(outB, out);

    // Feedback steps t = 1..31
    for (int t = 1; t < 32; t++) {
        // gx0 (K=512 -> 256/slice) | gh0 (K=2048 -> 1024/slice)
        gemm_tf32<3><<<dim3(GLD / TN, BSZ / TM, 2), 128, SMEM_BYTES>>>(
            outr, OUTD, i0, OUTD, 256,
            h0r,  HID,  r0, HID,  1024,
            G3H, g, GLD, PLANE, nullptr);
        gru_gates<<<gGates, 256>>>(g, bih0, bhh0, h0, h0r, 1);

        gemm_tf32<3><<<dim3(GLD / TN, BSZ / TM, 2), 128, SMEM_BYTES>>>(  // gx1|gh1
            h0r, HID, i1, HID, 1024,
            h1r, HID, r1, HID, 1024,
            G3H, g, GLD, PLANE, nullptr);
        gru_gates<<<gGates, 256>>>(g, bih1, bhh1, h1, h1r, 1);

        gemm_tf32<3><<<dim3(OUTD / TN, BSZ / TM, KSPLIT), 128, SMEM_BYTES>>>(
            h1r, HID, oW, HID, HID / KSPLIT,
            h1r, HID, oW, HID, HID / KSPLIT,
            BIG, part, OUTD, BSZ * OUTD, nullptr);
        out_reduce<<<(BSZ * OUTD / 4) / 256, 256>>>(outB, out + (size_t)t * OUTD);
    }
}

// round 13
// speedup vs baseline: 2.1722x; 1.7337x over previous
#include <cuda_runtime.h>
#include <cuda_fp16.h>
#include <cstdint>

// ---------------------------------------------------------------------------
// _LSTMOneMany_3289944948986 : 2-layer GRU decoder, B=512, H=2048, O=512, T=32.
// Round 13: fp16 mma.sync m16n8k16 (same 10-bit mantissa as tf32, 2x K per
// instruction -> GEMM instruction count halves). fp32 accumulate/state.
// R12 structure: 128x128 CTA, 4 warps of 64x64, LDSM, swizzled 3-stage
// cp.async (stage now covers K=64 halves, still 32KB), split-K=2 recurrent
// GEMMs, split-K=8 out projection.
// ---------------------------------------------------------------------------

#define BSZ   512
#define HID   2048
#define OUTD  512
#define G3H   6144
#define GLD   12288
#define PLANE (BSZ * GLD)
#define KSPLIT 8
#define TM    128
#define TN    128

typedef __half hf;

// ---- scratch (__device__ globals; no allocation allowed) ----
__device__ __align__(16) float g_g   [2 * PLANE];     // gate pre-acts, 2 K-planes
__device__ __align__(16) float g_h0  [BSZ * HID];     // exact fp32 state
__device__ __align__(16) float g_h1  [BSZ * HID];
__device__ __align__(16) hf    g_h0r [BSZ * HID];     // fp16 GEMM copies
__device__ __align__(16) hf    g_h1r [BSZ * HID];
__device__ __align__(16) hf    g_outr[BSZ * OUTD];    // fp16 feedback input
__device__ __align__(16) float g_part[KSPLIT * BSZ * OUTD];

// fp16 weights / inputs
__device__ __align__(16) hf w_x   [BSZ * 2 * 1024];
__device__ __align__(16) hf w_emb [2048 * 1024];
__device__ __align__(16) hf w_ih0 [G3H * OUTD];
__device__ __align__(16) hf w_hh0 [G3H * HID];
__device__ __align__(16) hf w_ih1 [G3H * HID];
__device__ __align__(16) hf w_hh1 [G3H * HID];
__device__ __align__(16) hf w_out [OUTD * HID];

// ---------------------------------------------------------------------------
// GEMM: C[M,N] = A[M,K] @ B[N,K]^T, fp16 operands, fp32 accum.
// 128x128 CTA tile, 128 threads (4 warps, 2x2 grid of 64x64 warp tiles),
// 3-stage cp.async; stage = [128r A | 128r B] x 64 halves (128 B/row),
// 16B-chunk XOR swizzle (chunk ^= row&7). mma m16n8k16.
// nSplit selects per-N-block source; K0/K1 are PER-Z-SLICE depths.
// MODE 2: embedding (bias+relu, scatter h0/h1 + fp16 copies), no z logic.
// MODE 3: z-sliced: koff = z*K, C += z*cStrideZ (split-K partial planes).
// ---------------------------------------------------------------------------
#define STAGE_HALVES (2 * 128 * 64)                // 16384 halves
#define STAGE_BYTES  (STAGE_HALVES * 2)            // 32768
static const int SMEM_BYTES = 3 * STAGE_BYTES;     // 98304

template <int MODE>
__global__ void __launch_bounds__(128, 2)
gemm_h(const hf* __restrict__ A0, int lda0,
       const hf* __restrict__ B0, int ldb0, int K0,
       const hf* __restrict__ A1, int lda1,
       const hf* __restrict__ B1, int ldb1, int K1,
       int nSplit,
       float* __restrict__ C, int ldc, int cStrideZ,
       const float* __restrict__ bias)
{
    extern __shared__ hf smem[];   // [3][A 128x64 | B 128x64] swizzled

    const int tid = threadIdx.x;
    const int bn  = blockIdx.x;
    const int bm  = blockIdx.y;
    const int nBase = bn * TN;

    const hf* A; const hf* B; int lda, ldb, K;
    if (nBase < nSplit) {
        A = A0; lda = lda0; B = B0 + (size_t)nBase * ldb0; ldb = ldb0; K = K0;
    } else {
        A = A1; lda = lda1; B = B1 + (size_t)(nBase - nSplit) * ldb1; ldb = ldb1; K = K1;
    }
    A += (size_t)bm * TM * lda;
    if (MODE == 3) {
        int koff = blockIdx.z * K;     // K is the per-slice depth
        A += koff; B += koff;
        C += (size_t)blockIdx.z * (size_t)cStrideZ;
    }

    const int lane = tid & 31;
    const int warp = tid >> 5;           // 0..3
    const int wm = (warp >> 1) << 6;     // 0 / 64
    const int wn = (warp & 1) << 6;      // 0 / 64
    const int lr = lane >> 2;            // 0..7
    const int lc = lane & 3;             // 0..3

    // ldmatrix lane roles
    const int lrow = lane & 7;
    const int lhlf = (lane >> 3) & 1;    // +8 rows
    const int lcol = (lane >> 4) & 1;    // +1 16B k-chunk (8 halves)

    // Per-site swizzled row constants (byte offsets within a stage; 128 B/row)
    uint32_t aRowB[4], bRowB[4];
    int aSw[4], bSw[4];
#pragma unroll
    for (int i = 0; i < 4; i++) {
        int ar = wm + i * 16 + lrow + lhlf * 8;
        aRowB[i] = (uint32_t)(ar * 128);
        aSw[i]   = ar & 7;
        int br = wn + i * 16 + lrow + lhlf * 8;
        bRowB[i] = (uint32_t)(128 * 128 + br * 128);
        bSw[i]   = br & 7;
    }
    const uint32_t smemBase = (uint32_t)__cvta_generic_to_shared(smem);

    float acc[4][8][4];
#pragma unroll
    for (int i = 0; i < 4; i++)
#pragma unroll
        for (int j = 0; j < 8; j++)
#pragma unroll
            for (int k = 0; k < 4; k++) acc[i][j][k] = 0.f;

    auto load_stage = [&](int buf, int k0) {
        hf* sA = smem + buf * STAGE_HALVES;
        hf* sB = sA + 128 * 64;
        const int tRow = tid >> 3;      // 0..15
        const int tCh  = tid & 7;       // 0..7
#pragma unroll
        for (int p = 0; p < 8; p++) {
            int row = tRow + p * 16;
            int dst = row * 64 + ((tCh ^ (row & 7)) << 3);   // halves
            uint32_t da = (uint32_t)__cvta_generic_to_shared(&sA[dst]);
            uint32_t db = (uint32_t)__cvta_generic_to_shared(&sB[dst]);
            asm volatile("cp.async.cg.shared.global [%0], [%1], 16;\n"
                         :: "r"(da), "l"(A + (size_t)row * lda + k0 + tCh * 8));
            asm volatile("cp.async.cg.shared.global [%0], [%1], 16;\n"
                         :: "r"(db), "l"(B + (size_t)row * ldb + k0 + tCh * 8));
        }
        asm volatile("cp.async.commit_group;\n");
    };

    const int nStages = K >> 6;        // K multiple of 256 everywhere -> >= 4
    load_stage(0, 0);
    load_stage(1, 64);
    int buf = 0;

    for (int st = 0; st < nStages; st++) {
        if (st + 2 < nStages) {
            load_stage((st + 2) % 3, (st + 2) * 64);
            asm volatile("cp.async.wait_group 2;\n");
        } else if (st + 1 < nStages) {
            asm volatile("cp.async.wait_group 1;\n");
        } else {
            asm volatile("cp.async.wait_group 0;\n");
        }
        __syncthreads();

        const uint32_t stBase = smemBase + (uint32_t)(buf * STAGE_BYTES);

#pragma unroll
        for (int kk = 0; kk < 4; kk++) {                 // 4 x k16 = K64
            const int kch = kk * 2 + lcol;               // 16B chunk index
            uint32_t af[4][4], bf[8][2];
#pragma unroll
            for (int mt = 0; mt < 4; mt++) {
                uint32_t ad = stBase + aRowB[mt] + (uint32_t)(((kch ^ aSw[mt]) << 4));
                asm volatile(
                    "ldmatrix.sync.aligned.m8n8.x4.shared.b16 {%0,%1,%2,%3}, [%4];\n"
                    : "=r"(af[mt][0]), "=r"(af[mt][1]),
                      "=r"(af[mt][2]), "=r"(af[mt][3])
                    : "r"(ad));
            }
#pragma unroll
            for (int n4 = 0; n4 < 4; n4++) {
                uint32_t bd = stBase + bRowB[n4] + (uint32_t)(((kch ^ bSw[n4]) << 4));
                asm volatile(
                    "ldmatrix.sync.aligned.m8n8.x4.shared.b16 {%0,%1,%2,%3}, [%4];\n"
                    : "=r"(bf[2 * n4][0]), "=r"(bf[2 * n4 + 1][0]),
                      "=r"(bf[2 * n4][1]), "=r"(bf[2 * n4 + 1][1])
                    : "r"(bd));
            }
#pragma unroll
            for (int mt = 0; mt < 4; mt++)
#pragma unroll
                for (int nt = 0; nt < 8; nt++) {
                    float* c = acc[mt][nt];
                    asm volatile(
                        "mma.sync.aligned.m16n8k16.row.col.f32.f16.f16.f32 "
                        "{%0,%1,%2,%3}, {%4,%5,%6,%7}, {%8,%9}, {%0,%1,%2,%3};\n"
                        : "+f"(c[0]), "+f"(c[1]), "+f"(c[2]), "+f"(c[3])
                        : "r"(af[mt][0]), "r"(af[mt][1]), "r"(af[mt][2]), "r"(af[mt][3]),
                          "r"(bf[nt][0]), "r"(bf[nt][1]));
                }
        }
        __syncthreads();
        buf = (buf + 1) % 3;
    }

    // -------- epilogue --------
#pragma unroll
    for (int mt = 0; mt < 4; mt++)
#pragma unroll
        for (int nt = 0; nt < 8; nt++) {
            int m = bm * TM + wm + mt * 16 + lr;
            int n = nBase + wn + nt * 8 + lc * 2;
            float2 v0 = make_float2(acc[mt][nt][0], acc[mt][nt][1]);
            float2 v1 = make_float2(acc[mt][nt][2], acc[mt][nt][3]);
            if (MODE == 3) {
                *(float2*)&C[(size_t)m       * ldc + n] = v0;
                *(float2*)&C[(size_t)(m + 8) * ldc + n] = v1;
            } else {  // MODE 2: embedding -> relu; scatter to h0/h1 (+ fp16)
                float b0 = bias[n], b1 = bias[n + 1];
                v0.x = fmaxf(v0.x + b0, 0.f); v0.y = fmaxf(v0.y + b1, 0.f);
                v1.x = fmaxf(v1.x + b0, 0.f); v1.y = fmaxf(v1.y + b1, 0.f);
                float* hp = (m & 1) ? g_h1  : g_h0;
                hf*    hr = (m & 1) ? g_h1r : g_h0r;
                size_t o0 = (size_t)(m >> 1) * HID + n;
                size_t o1 = o0 + 4 * HID;              // rows m, m+8 same parity
                *(float2*)&hp[o0] = v0;
                *(float2*)&hp[o1] = v1;
                *(__half2*)&hr[o0] = __floats2half2_rn(v0.x, v0.y);
                *(__half2*)&hr[o1] = __floats2half2_rn(v1.x, v1.y);
            }
        }
}

// ---------------------------------------------------------------------------
// GRU gates (float4): sums the two split-K planes of g, then
// r=sig(gx_r+gh_r), z=sig(gx_z+gh_z), n=tanh(gx_n+r*gh_n), h=(1-z)n+z*h.
// Writes exact fp32 h + fp16 copy for the next GEMM.
// ---------------------------------------------------------------------------
__global__ void __launch_bounds__(256)
gru_gates(const float* __restrict__ g,
          const float* __restrict__ bih, const float* __restrict__ bhh,
          float* __restrict__ h, hf* __restrict__ hr, int hasGx)
{
    int idx = (blockIdx.x * 256 + threadIdx.x) * 4;   // < 512*2048
    int b = idx >> 11, j = idx & 2047;
    const float* g0 = g + (size_t)b * GLD;
    const float* g1 = g0 + PLANE;

    float4 gxr = *(const float4*)&bih[j];
    float4 gxz = *(const float4*)&bih[HID + j];
    float4 gxn = *(const float4*)&bih[2 * HID + j];
    if (hasGx) {
#pragma unroll
        for (int pl = 0; pl < 2; pl++) {
            const float* gp = pl ? g1 : g0;
            float4 a = *(const float4*)&gp[j];
            float4 c = *(const float4*)&gp[HID + j];
            float4 d = *(const float4*)&gp[2 * HID + j];
            gxr.x += a.x; gxr.y += a.y; gxr.z += a.z; gxr.w += a.w;
            gxz.x += c.x; gxz.y += c.y; gxz.z += c.z; gxz.w += c.w;
            gxn.x += d.x; gxn.y += d.y; gxn.z += d.z; gxn.w += d.w;
        }
    }
    float4 ghr = *(const float4*)&bhh[j];
    float4 ghz = *(const float4*)&bhh[HID + j];
    float4 ghn = *(const float4*)&bhh[2 * HID + j];
#pragma unroll
    for (int pl = 0; pl < 2; pl++) {
        const float* gp = pl ? g1 : g0;
        float4 a = *(const float4*)&gp[G3H + j];
        float4 c = *(const float4*)&gp[G3H + HID + j];
        float4 d = *(const float4*)&gp[G3H + 2 * HID + j];
        ghr.x += a.x; ghr.y += a.y; ghr.z += a.z; ghr.w += a.w;
        ghz.x += c.x; ghz.y += c.y; ghz.z += c.z; ghz.w += c.w;
        ghn.x += d.x; ghn.y += d.y; ghn.z += d.z; ghn.w += d.w;
    }
    float4 hp = *(const float4*)&h[idx];

    float4 ho;
    float hv4[4];
#pragma unroll
    for (int q = 0; q < 4; q++) {
        float xr = ((float*)&gxr)[q], xz = ((float*)&gxz)[q], xn = ((float*)&gxn)[q];
        float vr = ((float*)&ghr)[q];
        float vz = ((float*)&ghz)[q];
        float vn = ((float*)&ghn)[q];
        float r = 1.f / (1.f + expf(-(xr + vr)));
        float z = 1.f / (1.f + expf(-(xz + vz)));
        float n = tanhf(xn + r * vn);
        float hv = (1.f - z) * n + z * ((float*)&hp)[q];
        ((float*)&ho)[q] = hv;
        hv4[q] = hv;
    }
    *(float4*)&h[idx] = ho;
    *(__half2*)&hr[idx]     = __floats2half2_rn(hv4[0], hv4[1]);
    *(__half2*)&hr[idx + 2] = __floats2half2_rn(hv4[2], hv4[3]);
}

// Reduce split-K partials + bias -> exact preds slice + fp16 feedback buf.
__global__ void __launch_bounds__(256)
out_reduce(const float* __restrict__ outB, float* __restrict__ preds)
{
    int idx = (blockIdx.x * 256 + threadIdx.x) * 4;   // < 512*512
    int o = idx & 511, b = idx >> 9;
    float4 v = *(const float4*)&outB[o];
#pragma unroll
    for (int z = 0; z < KSPLIT; z++) {
        float4 pz = *(const float4*)&g_part[z * (BSZ * OUTD) + idx];
        v.x += pz.x; v.y += pz.y; v.z += pz.z; v.w += pz.w;
    }
    *(float4*)&preds[(size_t)b * (32 * OUTD) + o] = v;
    *(__half2*)&g_outr[idx]     = __floats2half2_rn(v.x, v.y);
    *(__half2*)&g_outr[idx + 2] = __floats2half2_rn(v.z, v.w);
}

// fp32 -> fp16, 4 segments per launch
__global__ void __launch_bounds__(256)
conv4(const float* s0, hf* d0, int n0, const float* s1, hf* d1, int n1,
      const float* s2, hf* d2, int n2, const float* s3, hf* d3, int n3)
{
    int i = blockIdx.x * 256 + threadIdx.x;
    if      (i < n0)         d0[i] = __float2half_rn(s0[i]);
    else if ((i -= n0) < n1) d1[i] = __float2half_rn(s1[i]);
    else if ((i -= n1) < n2) d2[i] = __float2half_rn(s2[i]);
    else if ((i -= n2) < n3) d3[i] = __float2half_rn(s3[i]);
}

// ---------------------------------------------------------------------------

extern "C" void kernel_launch(void* const* d_in, const int* in_sizes, int n_in,
                              void* d_out, int out_size)
{
    const float* x    = (const float*)d_in[0];
    const float* embB = (const float*)d_in[2];
    const float* bih0 = (const float*)d_in[5];
    const float* bhh0 = (const float*)d_in[6];
    const float* bih1 = (const float*)d_in[9];
    const float* bhh1 = (const float*)d_in[10];
    const float* outB = (const float*)d_in[12];
    float* out = (float*)d_out;                  // [512, 32, 512]

    cudaFuncSetAttribute(gemm_h<2>,
                         cudaFuncAttributeMaxDynamicSharedMemorySize, SMEM_BYTES);
    cudaFuncSetAttribute(gemm_h<3>,
                         cudaFuncAttributeMaxDynamicSharedMemorySize, SMEM_BYTES);

    void* p;
    cudaGetSymbolAddress(&p, g_g);    float* g    = (float*)p;
    cudaGetSymbolAddress(&p, g_h0);   float* h0   = (float*)p;
    cudaGetSymbolAddress(&p, g_h1);   float* h1   = (float*)p;
    cudaGetSymbolAddress(&p, g_h0r);  hf*    h0r  = (hf*)p;
    cudaGetSymbolAddress(&p, g_h1r);  hf*    h1r  = (hf*)p;
    cudaGetSymbolAddress(&p, g_outr); hf*    outr = (hf*)p;
    cudaGetSymbolAddress(&p, g_part); float* part = (float*)p;
    cudaGetSymbolAddress(&p, w_x);    hf*    xr   = (hf*)p;
    cudaGetSymbolAddress(&p, w_emb);  hf*    eW   = (hf*)p;
    cudaGetSymbolAddress(&p, w_ih0);  hf*    i0   = (hf*)p;
    cudaGetSymbolAddress(&p, w_hh0);  hf*    r0   = (hf*)p;
    cudaGetSymbolAddress(&p, w_ih1);  hf*    i1   = (hf*)p;
    cudaGetSymbolAddress(&p, w_hh1);  hf*    r1   = (hf*)p;
    cudaGetSymbolAddress(&p, w_out);  hf*    oW   = (hf*)p;

    const int BIG = 1 << 30;
    const dim3 gGates((BSZ * HID / 4) / 256);

    // [0][1] fp32->fp16 conversions in two launches
    {
        const int n0 = BSZ * 2 * 1024, n1 = 2048 * 1024;
        const int n2 = G3H * OUTD,     n3 = OUTD * HID;
        int tA = n0 + n1 + n2 + n3;
        conv4<<<(tA + 255) / 256, 256>>>(
            x, xr, n0, (const float*)d_in[1], eW, n1,
            (const float*)d_in[3], i0, n2, (const float*)d_in[11], oW, n3);

        const int m0 = G3H * HID;
        int tB = 3 * m0;
        conv4<<<(tB + 255) / 256, 256>>>(
            (const float*)d_in[4], r0, m0, (const float*)d_in[7], i1, m0,
            (const float*)d_in[8], r1, m0, (const float*)d_in[8], r1, 0);
    }

    // [2] Embedding: M=1024 (b*2+l), N=2048, K=1024 -> relu -> h0/h1 + fp16
    gemm_h<2><<<dim3(2048 / TN, 1024 / TM), 128, SMEM_BYTES>>>(
        xr, 1024, eW, 1024, 1024,
        xr, 1024, eW, 1024, 1024,
        BIG, nullptr, 0, 0, embB);

    // [3..] 2 warmup steps (zero input: gx0 skipped, gates use bias only)
    for (int w = 0; w < 2; w++) {
        // gh0, split-K=2: per-slice K=1024, planes at g / g+PLANE (col G3H)
        gemm_h<3><<<dim3(G3H / TN, BSZ / TM, 2), 128, SMEM_BYTES>>>(
            h0r, HID, r0, HID, 1024,
            h0r, HID, r0, HID, 1024,
            BIG, g + G3H, GLD, PLANE, nullptr);
        gru_gates<<<gGates, 256>>>(g, bih0, bhh0, h0, h0r, 0);

        // launch index 5 on w==0: main-loop-sized GEMM (for ncu -s 5 -c 1)
        gemm_h<3><<<dim3(GLD / TN, BSZ / TM, 2), 128, SMEM_BYTES>>>(  // gx1|gh1
            h0r, HID, i1, HID, 1024,
            h1r, HID, r1, HID, 1024,
            G3H, g, GLD, PLANE, nullptr);
        gru_gates<<<gGates, 256>>>(g, bih1, bhh1, h1, h1r, 1);
    }

    // out0 (split-K=8) -> preds[:,0,:] + fp16 feedback
    gemm_h<3><<<dim3(OUTD / TN, BSZ / TM, KSPLIT), 128, SMEM_BYTES>>>(
        h1r, HID, oW, HID, HID / KSPLIT,
        h1r, HID, oW, HID, HID / KSPLIT,
        BIG, part, OUTD, BSZ * OUTD, nullptr);
    out_reduce<<<(BSZ * OUTD / 4) / 256, 256>>>(outB, out);

    // Feedback steps t = 1..31
    for (int t = 1; t < 32; t++) {
        // gx0 (K=512 -> 256/slice) | gh0 (K=2048 -> 1024/slice)
        gemm_h<3><<<dim3(GLD / TN, BSZ / TM, 2), 128, SMEM_BYTES>>>(
            outr, OUTD, i0, OUTD, 256,
            h0r,  HID,  r0, HID,  1024,
            G3H, g, GLD, PLANE, nullptr);
        gru_gates<<<gGates, 256>>>(g, bih0, bhh0, h0, h0r, 1);

        gemm_h<3><<<dim3(GLD / TN, BSZ / TM, 2), 128, SMEM_BYTES>>>(  // gx1|gh1
            h0r, HID, i1, HID, 1024,
            h1r, HID, r1, HID, 1024,
            G3H, g, GLD, PLANE, nullptr);
        gru_gates<<<gGates, 256>>>(g, bih1, bhh1, h1, h1r, 1);

        gemm_h<3><<<dim3(OUTD / TN, BSZ / TM, KSPLIT), 128, SMEM_BYTES>>>(
            h1r, HID, oW, HID, HID / KSPLIT,
            h1r, HID, oW, HID, HID / KSPLIT,
            BIG, part, OUTD, BSZ * OUTD, nullptr);
        out_reduce<<<(BSZ * OUTD / 4) / 256, 256>>>(outB, out + (size_t)t * OUTD);
    }
}